// round 1
// baseline (speedup 1.0000x reference)
#include <cuda_runtime.h>
#include <math.h>

#define T_ 1024
#define H_ 1024
#define I_ 1024
#define E_ 8
#define NP (T_*2)       // token-expert pairs (top_k = 2)

#define BM 128
#define BN 64
#define BK 16
#define MAXMT 16        // ceil(NP/BM): worst case all pairs on one expert

// ---- scratch (no allocations allowed) ----
__device__ int   g_pair_e[NP];
__device__ float g_pair_w[NP];
__device__ int   g_counts[E_];
__device__ int   g_offsets[E_+1];
__device__ int   g_cursor[E_];
__device__ int   g_perm[NP];
__device__ float g_act[(size_t)NP * I_];   // 8 MB intermediate (silu(gate)*up)

// ---------------------------------------------------------------------------
// zero output + reset routing counters
// ---------------------------------------------------------------------------
__global__ void k_zero(float* __restrict__ out) {
    int i = blockIdx.x * blockDim.x + threadIdx.x;   // T_*H_/4 slots
    float4 z = make_float4(0.f, 0.f, 0.f, 0.f);
    ((float4*)out)[i] = z;
    if (blockIdx.x == 0 && threadIdx.x < E_) {
        g_counts[threadIdx.x] = 0;
        g_cursor[threadIdx.x] = 0;
    }
}

// ---------------------------------------------------------------------------
// routing: top-2 of logits == top-2 of softmax; renormalized weights are a
// 2-term softmax of the two winning logits.
// ---------------------------------------------------------------------------
__global__ void k_route(const float* __restrict__ logits) {
    int t = blockIdx.x * blockDim.x + threadIdx.x;
    if (t >= T_) return;
    float l[E_];
#pragma unroll
    for (int e = 0; e < E_; e++) l[e] = logits[t * E_ + e];
    int i0 = 0;
#pragma unroll
    for (int e = 1; e < E_; e++) if (l[e] > l[i0]) i0 = e;   // strict > : lowest idx wins ties (jax order)
    int i1 = -1;
#pragma unroll
    for (int e = 0; e < E_; e++)
        if (e != i0 && (i1 < 0 || l[e] > l[i1])) i1 = e;
    float w0 = 1.f / (1.f + expf(l[i1] - l[i0]));
    float w1 = 1.f / (1.f + expf(l[i0] - l[i1]));
    g_pair_e[2 * t]     = i0;  g_pair_w[2 * t]     = w0;
    g_pair_e[2 * t + 1] = i1;  g_pair_w[2 * t + 1] = w1;
    atomicAdd(&g_counts[i0], 1);
    atomicAdd(&g_counts[i1], 1);
}

__global__ void k_scan() {
    if (threadIdx.x == 0) {
        int o = 0;
        for (int e = 0; e < E_; e++) { g_offsets[e] = o; o += g_counts[e]; }
        g_offsets[E_] = o;
    }
}

__global__ void k_scatter() {
    int p = blockIdx.x * blockDim.x + threadIdx.x;
    if (p >= NP) return;
    int e = g_pair_e[p];
    int pos = atomicAdd(&g_cursor[e], 1);
    g_perm[g_offsets[e] + pos] = p;
}

// ---------------------------------------------------------------------------
// GEMM1: for expert-grouped rows, compute gate = X@W13[:, :I], up = X@W13[:, I:]
// over a BN-wide column slab; fuse silu(gate)*up into g_act.
// grid: (I_/BN, E_*MAXMT), 256 threads, thread tile 8x4 (x2 for gate/up).
// ---------------------------------------------------------------------------
__global__ __launch_bounds__(256) void k_gemm1(const float* __restrict__ hid,
                                               const float* __restrict__ W13) {
    __shared__ int s_pair[BM];
    __shared__ __align__(16) float As[BK][BM + 4];
    __shared__ __align__(16) float Bg[BK][BN];
    __shared__ __align__(16) float Bu[BK][BN];

    int e  = blockIdx.y >> 4;
    int mt = blockIdx.y & 15;
    int off = g_offsets[e];
    int cnt = g_offsets[e + 1] - off;
    int row0 = mt * BM;
    if (row0 >= cnt) return;

    int tid = threadIdx.x;
    if (tid < BM) {
        int r = row0 + tid;
        s_pair[tid] = (r < cnt) ? g_perm[off + r] : -1;
    }
    __syncthreads();

    int n0glob = blockIdx.x * BN;
    const float* Wg = W13 + (size_t)e * H_ * (2 * I_) + n0glob;
    const float* Wu = Wg + I_;

    float accg[8][4], accu[8][4];
#pragma unroll
    for (int i = 0; i < 8; i++)
#pragma unroll
        for (int j = 0; j < 4; j++) { accg[i][j] = 0.f; accu[i][j] = 0.f; }

    int ty = tid >> 4, tx = tid & 15;
    int m0 = ty * 8, n0 = tx * 4;

    for (int k0 = 0; k0 < H_; k0 += BK) {
        // A tile (gathered rows), transposed into As[k][m]
#pragma unroll
        for (int i = 0; i < 2; i++) {
            int idx = tid + i * 256;            // 0..511
            int m = idx >> 2;
            int kk = (idx & 3) * 4;
            int p = s_pair[m];
            float4 v = make_float4(0.f, 0.f, 0.f, 0.f);
            if (p >= 0)
                v = *(const float4*)&hid[(size_t)(p >> 1) * H_ + k0 + kk];
            As[kk + 0][m] = v.x; As[kk + 1][m] = v.y;
            As[kk + 2][m] = v.z; As[kk + 3][m] = v.w;
        }
        // B tiles (gate + up)
        {
            int kk = tid >> 4;
            int nn = (tid & 15) * 4;
            *(float4*)&Bg[kk][nn] = *(const float4*)&Wg[(size_t)(k0 + kk) * (2 * I_) + nn];
            *(float4*)&Bu[kk][nn] = *(const float4*)&Wu[(size_t)(k0 + kk) * (2 * I_) + nn];
        }
        __syncthreads();

#pragma unroll
        for (int kk = 0; kk < BK; kk++) {
            float a[8], bg[4], bu[4];
            *(float4*)&a[0] = *(float4*)&As[kk][m0];
            *(float4*)&a[4] = *(float4*)&As[kk][m0 + 4];
            *(float4*)&bg[0] = *(float4*)&Bg[kk][n0];
            *(float4*)&bu[0] = *(float4*)&Bu[kk][n0];
#pragma unroll
            for (int mi = 0; mi < 8; mi++)
#pragma unroll
                for (int ni = 0; ni < 4; ni++) {
                    accg[mi][ni] += a[mi] * bg[ni];
                    accu[mi][ni] += a[mi] * bu[ni];
                }
        }
        __syncthreads();
    }

#pragma unroll
    for (int mi = 0; mi < 8; mi++) {
        int p = s_pair[m0 + mi];
        if (p < 0) continue;
        float* dst = g_act + (size_t)p * I_ + n0glob + n0;
#pragma unroll
        for (int ni = 0; ni < 4; ni++) {
            float g = accg[mi][ni];
            float u = accu[mi][ni];
            float s = g / (1.f + expf(-g));     // silu
            dst[ni] = s * u;
        }
    }
}

// ---------------------------------------------------------------------------
// GEMM2: down-proj act @ W2[e], weighted scatter-add into out (exactly 2
// contributions per output element -> commutative -> deterministic).
// ---------------------------------------------------------------------------
__global__ __launch_bounds__(256) void k_gemm2(const float* __restrict__ W2,
                                               float* __restrict__ out) {
    __shared__ int s_pair[BM];
    __shared__ __align__(16) float As[BK][BM + 4];
    __shared__ __align__(16) float Bs[BK][BN];

    int e  = blockIdx.y >> 4;
    int mt = blockIdx.y & 15;
    int off = g_offsets[e];
    int cnt = g_offsets[e + 1] - off;
    int row0 = mt * BM;
    if (row0 >= cnt) return;

    int tid = threadIdx.x;
    if (tid < BM) {
        int r = row0 + tid;
        s_pair[tid] = (r < cnt) ? g_perm[off + r] : -1;
    }
    __syncthreads();

    int n0glob = blockIdx.x * BN;
    const float* Wb = W2 + (size_t)e * I_ * H_ + n0glob;

    float acc[8][4];
#pragma unroll
    for (int i = 0; i < 8; i++)
#pragma unroll
        for (int j = 0; j < 4; j++) acc[i][j] = 0.f;

    int ty = tid >> 4, tx = tid & 15;
    int m0 = ty * 8, n0 = tx * 4;

    for (int k0 = 0; k0 < I_; k0 += BK) {
#pragma unroll
        for (int i = 0; i < 2; i++) {
            int idx = tid + i * 256;
            int m = idx >> 2;
            int kk = (idx & 3) * 4;
            int p = s_pair[m];
            float4 v = make_float4(0.f, 0.f, 0.f, 0.f);
            if (p >= 0)
                v = *(const float4*)&g_act[(size_t)p * I_ + k0 + kk];
            As[kk + 0][m] = v.x; As[kk + 1][m] = v.y;
            As[kk + 2][m] = v.z; As[kk + 3][m] = v.w;
        }
        {
            int kk = tid >> 4;
            int nn = (tid & 15) * 4;
            *(float4*)&Bs[kk][nn] = *(const float4*)&Wb[(size_t)(k0 + kk) * H_ + nn];
        }
        __syncthreads();

#pragma unroll
        for (int kk = 0; kk < BK; kk++) {
            float a[8], b[4];
            *(float4*)&a[0] = *(float4*)&As[kk][m0];
            *(float4*)&a[4] = *(float4*)&As[kk][m0 + 4];
            *(float4*)&b[0] = *(float4*)&Bs[kk][n0];
#pragma unroll
            for (int mi = 0; mi < 8; mi++)
#pragma unroll
                for (int ni = 0; ni < 4; ni++)
                    acc[mi][ni] += a[mi] * b[ni];
        }
        __syncthreads();
    }

#pragma unroll
    for (int mi = 0; mi < 8; mi++) {
        int p = s_pair[m0 + mi];
        if (p < 0) continue;
        int t = p >> 1;
        float w = g_pair_w[p];
        float* dst = out + (size_t)t * H_ + n0glob + n0;
#pragma unroll
        for (int ni = 0; ni < 4; ni++)
            atomicAdd(&dst[ni], w * acc[mi][ni]);
    }
}

// ---------------------------------------------------------------------------
extern "C" void kernel_launch(void* const* d_in, const int* in_sizes, int n_in,
                              void* d_out, int out_size) {
    const float* hid    = (const float*)d_in[0];   // [T, H]
    const float* logits = (const float*)d_in[1];   // [T, E]
    const float* W13    = (const float*)d_in[2];   // [E, H, 2I]
    const float* W2     = (const float*)d_in[3];   // [E, I, H]
    float* out = (float*)d_out;                    // [T, H] fp32

    k_zero<<<(T_ * H_ / 4) / 256, 256>>>(out);
    k_route<<<(T_ + 255) / 256, 256>>>(logits);
    k_scan<<<1, 32>>>();
    k_scatter<<<(NP + 255) / 256, 256>>>();

    dim3 g1(I_ / BN, E_ * MAXMT);
    k_gemm1<<<g1, 256>>>(hid, W13);
    dim3 g2(H_ / BN, E_ * MAXMT);
    k_gemm2<<<g2, 256>>>(W2, out);
}

// round 2
// speedup vs baseline: 1.3468x; 1.3468x over previous
#include <cuda_runtime.h>
#include <cuda_bf16.h>
#include <math.h>

#define T_ 1024
#define H_ 1024
#define I_ 1024
#define E_ 8
#define NP (T_*2)       // token-expert pairs (top_k = 2)

#define BM 128
#define BN 64
#define BK 32
#define BKP 16          // BK/2 packed k-pairs
#define RS 20           // smem row stride in uint32 (conflict-free frag reads)
#define MAXMT 16        // ceil(NP/BM) worst case

// ---- scratch ----
__device__ float g_pair_w[NP];
__device__ int   g_offsets[E_+1];
__device__ int   g_perm[NP];
__device__ float g_act[(size_t)NP * I_];   // 8 MB silu(gate)*up

// ---------------------------------------------------------------------------
// helpers
// ---------------------------------------------------------------------------
__device__ __forceinline__ unsigned pack_rn(float x, float y) {
    __nv_bfloat162 v = __floats2bfloat162_rn(x, y);
    return *(unsigned*)&v;
}
__device__ __forceinline__ void split_pack(float x, float y, unsigned& hi, unsigned& lo) {
    hi = pack_rn(x, y);
    __nv_bfloat162 hv = *(__nv_bfloat162*)&hi;
    float xr = x - __bfloat162float(hv.x);
    float yr = y - __bfloat162float(hv.y);
    lo = pack_rn(xr, yr);
}

#define MMA(c, a, b0_, b1_)                                                   \
    asm volatile("mma.sync.aligned.m16n8k16.row.col.f32.bf16.bf16.f32 "       \
        "{%0,%1,%2,%3}, {%4,%5,%6,%7}, {%8,%9}, {%0,%1,%2,%3};"               \
        : "+f"((c)[0]), "+f"((c)[1]), "+f"((c)[2]), "+f"((c)[3])              \
        : "r"((a)[0]), "r"((a)[1]), "r"((a)[2]), "r"((a)[3]),                 \
          "r"(b0_), "r"(b1_))

// ---------------------------------------------------------------------------
// zero output (needed: gemm2 scatters with atomicAdd)
// ---------------------------------------------------------------------------
__global__ void k_zero(float* __restrict__ out) {
    int i = blockIdx.x * blockDim.x + threadIdx.x;
    ((float4*)out)[i] = make_float4(0.f, 0.f, 0.f, 0.f);
}

// ---------------------------------------------------------------------------
// fused routing: top-2 + 2-term softmax weights + counting sort, one block
// ---------------------------------------------------------------------------
__global__ void k_route(const float* __restrict__ logits) {
    __shared__ int cnt[E_], cur[E_], soff[E_ + 1];
    int t = threadIdx.x;                 // 1024 threads == T_
    if (t < E_) { cnt[t] = 0; cur[t] = 0; }
    __syncthreads();

    float l[E_];
#pragma unroll
    for (int e = 0; e < E_; e++) l[e] = logits[t * E_ + e];
    int i0 = 0;
#pragma unroll
    for (int e = 1; e < E_; e++) if (l[e] > l[i0]) i0 = e;
    int i1 = -1;
#pragma unroll
    for (int e = 0; e < E_; e++)
        if (e != i0 && (i1 < 0 || l[e] > l[i1])) i1 = e;
    float w0 = 1.f / (1.f + expf(l[i1] - l[i0]));
    float w1 = 1.f / (1.f + expf(l[i0] - l[i1]));
    g_pair_w[2 * t]     = w0;
    g_pair_w[2 * t + 1] = w1;
    atomicAdd(&cnt[i0], 1);
    atomicAdd(&cnt[i1], 1);
    __syncthreads();

    if (t == 0) {
        int o = 0;
        for (int e = 0; e < E_; e++) { soff[e] = o; o += cnt[e]; }
        soff[E_] = o;
    }
    __syncthreads();
    if (t <= E_) g_offsets[t] = soff[t];

    int p0 = atomicAdd(&cur[i0], 1);
    g_perm[soff[i0] + p0] = 2 * t;
    int p1 = atomicAdd(&cur[i1], 1);
    g_perm[soff[i1] + p1] = 2 * t + 1;
}

// ---------------------------------------------------------------------------
// GEMM1 (tensor cores): act[p, n] = silu(X@Wg) * (X@Wu), expert-grouped rows.
// bf16 hi/lo split, 3 MMAs per tile pair. grid (I/BN, E*MAXMT), 256 thr.
// smem layout: packed k-pairs, addr = row*RS + kp  (conflict-free frag LDS).
// ---------------------------------------------------------------------------
__global__ __launch_bounds__(256) void k_gemm1(const float* __restrict__ hid,
                                               const float* __restrict__ W13) {
    __shared__ int s_pair[BM];
    __shared__ unsigned sAh[BM * RS], sAl[BM * RS];
    __shared__ unsigned sBgh[BN * RS], sBgl[BN * RS];
    __shared__ unsigned sBuh[BN * RS], sBul[BN * RS];

    int e  = blockIdx.y >> 4;
    int mt = blockIdx.y & 15;
    int off = g_offsets[e];
    int cnt = g_offsets[e + 1] - off;
    int row0 = mt * BM;
    if (row0 >= cnt) return;

    int tid = threadIdx.x;
    if (tid < BM) {
        int r = row0 + tid;
        s_pair[tid] = (r < cnt) ? g_perm[off + r] : -1;
    }
    __syncthreads();

    int n0glob = blockIdx.x * BN;
    const float* Wg = W13 + (size_t)e * H_ * (2 * I_) + n0glob;

    int wid = tid >> 5, lane = tid & 31;
    int wm = wid >> 2, wn = wid & 3;        // 2 x 4 warp grid
    int g = lane >> 2, tg = lane & 3;

    float cg[4][2][4], cu[4][2][4];
#pragma unroll
    for (int a = 0; a < 4; a++)
#pragma unroll
        for (int b = 0; b < 2; b++)
#pragma unroll
            for (int c = 0; c < 4; c++) { cg[a][b][c] = 0.f; cu[a][b][c] = 0.f; }

    for (int k0 = 0; k0 < H_; k0 += BK) {
        // A tile: gather rows, split fp32 -> bf16 hi/lo k-pairs
#pragma unroll
        for (int it = 0; it < 8; it++) {
            int m  = (tid >> 4) + it * 16;
            int kp = tid & 15;
            int p  = s_pair[m];
            float2 v = make_float2(0.f, 0.f);
            if (p >= 0)
                v = *(const float2*)&hid[(size_t)(p >> 1) * H_ + k0 + 2 * kp];
            unsigned h_, l_;
            split_pack(v.x, v.y, h_, l_);
            sAh[m * RS + kp] = h_;
            sAl[m * RS + kp] = l_;
        }
        // B tiles: gate + up, k-pair rows (two gmem rows per entry)
#pragma unroll
        for (int it = 0; it < 4; it++) {
            int n  = tid & 63;
            int kp = (tid >> 6) + it * 4;
            const float* bp = Wg + (size_t)(k0 + 2 * kp) * (2 * I_) + n;
            unsigned h_, l_;
            split_pack(bp[0], bp[2 * I_], h_, l_);
            sBgh[n * RS + kp] = h_;
            sBgl[n * RS + kp] = l_;
            split_pack(bp[I_], bp[2 * I_ + I_], h_, l_);
            sBuh[n * RS + kp] = h_;
            sBul[n * RS + kp] = l_;
        }
        __syncthreads();

#pragma unroll
        for (int ks = 0; ks < 2; ks++) {
            int kp0 = ks * 8;
            unsigned bgh[2][2], bgl[2][2], buh[2][2], bul[2][2];
#pragma unroll
            for (int nf = 0; nf < 2; nf++) {
                int cb = (wn * 16 + nf * 8 + g) * RS + kp0 + tg;
                bgh[nf][0] = sBgh[cb]; bgh[nf][1] = sBgh[cb + 4];
                bgl[nf][0] = sBgl[cb]; bgl[nf][1] = sBgl[cb + 4];
                buh[nf][0] = sBuh[cb]; buh[nf][1] = sBuh[cb + 4];
                bul[nf][0] = sBul[cb]; bul[nf][1] = sBul[cb + 4];
            }
#pragma unroll
            for (int mf = 0; mf < 4; mf++) {
                int r0 = (wm * 64 + mf * 16 + g) * RS + kp0 + tg;
                int r1 = r0 + 8 * RS;
                unsigned ah[4] = {sAh[r0], sAh[r1], sAh[r0 + 4], sAh[r1 + 4]};
                unsigned al[4] = {sAl[r0], sAl[r1], sAl[r0 + 4], sAl[r1 + 4]};
#pragma unroll
                for (int nf = 0; nf < 2; nf++) {
                    MMA(cg[mf][nf], ah, bgh[nf][0], bgh[nf][1]);
                    MMA(cg[mf][nf], ah, bgl[nf][0], bgl[nf][1]);
                    MMA(cg[mf][nf], al, bgh[nf][0], bgh[nf][1]);
                    MMA(cu[mf][nf], ah, buh[nf][0], buh[nf][1]);
                    MMA(cu[mf][nf], ah, bul[nf][0], bul[nf][1]);
                    MMA(cu[mf][nf], al, buh[nf][0], buh[nf][1]);
                }
            }
        }
        __syncthreads();
    }

    // epilogue: silu(gate)*up -> g_act
#pragma unroll
    for (int mf = 0; mf < 4; mf++) {
        int rb = wm * 64 + mf * 16 + g;
#pragma unroll
        for (int half = 0; half < 2; half++) {
            int p = s_pair[rb + half * 8];
            if (p < 0) continue;
            float* dst = g_act + (size_t)p * I_ + n0glob + wn * 16 + 2 * tg;
#pragma unroll
            for (int nf = 0; nf < 2; nf++) {
                float gv0 = cg[mf][nf][half * 2 + 0];
                float gv1 = cg[mf][nf][half * 2 + 1];
                float uv0 = cu[mf][nf][half * 2 + 0];
                float uv1 = cu[mf][nf][half * 2 + 1];
                float s0 = gv0 / (1.f + expf(-gv0));
                float s1 = gv1 / (1.f + expf(-gv1));
                *(float2*)&dst[nf * 8] = make_float2(s0 * uv0, s1 * uv1);
            }
        }
    }
}

// ---------------------------------------------------------------------------
// GEMM2 (tensor cores): out[t] += w_p * (act[p] @ W2[e]); weighted atomic
// scatter (exactly 2 commutative contributions per element -> deterministic).
// ---------------------------------------------------------------------------
__global__ __launch_bounds__(256) void k_gemm2(const float* __restrict__ W2,
                                               float* __restrict__ out) {
    __shared__ int s_pair[BM];
    __shared__ unsigned sAh[BM * RS], sAl[BM * RS];
    __shared__ unsigned sBh[BN * RS], sBl[BN * RS];

    int e  = blockIdx.y >> 4;
    int mt = blockIdx.y & 15;
    int off = g_offsets[e];
    int cnt = g_offsets[e + 1] - off;
    int row0 = mt * BM;
    if (row0 >= cnt) return;

    int tid = threadIdx.x;
    if (tid < BM) {
        int r = row0 + tid;
        s_pair[tid] = (r < cnt) ? g_perm[off + r] : -1;
    }
    __syncthreads();

    int n0glob = blockIdx.x * BN;
    const float* Wb = W2 + (size_t)e * I_ * H_ + n0glob;

    int wid = tid >> 5, lane = tid & 31;
    int wm = wid >> 2, wn = wid & 3;
    int g = lane >> 2, tg = lane & 3;

    float cc[4][2][4];
#pragma unroll
    for (int a = 0; a < 4; a++)
#pragma unroll
        for (int b = 0; b < 2; b++)
#pragma unroll
            for (int c = 0; c < 4; c++) cc[a][b][c] = 0.f;

    for (int k0 = 0; k0 < I_; k0 += BK) {
#pragma unroll
        for (int it = 0; it < 8; it++) {
            int m  = (tid >> 4) + it * 16;
            int kp = tid & 15;
            int p  = s_pair[m];
            float2 v = make_float2(0.f, 0.f);
            if (p >= 0)
                v = *(const float2*)&g_act[(size_t)p * I_ + k0 + 2 * kp];
            unsigned h_, l_;
            split_pack(v.x, v.y, h_, l_);
            sAh[m * RS + kp] = h_;
            sAl[m * RS + kp] = l_;
        }
#pragma unroll
        for (int it = 0; it < 4; it++) {
            int n  = tid & 63;
            int kp = (tid >> 6) + it * 4;
            const float* bp = Wb + (size_t)(k0 + 2 * kp) * H_ + n;
            unsigned h_, l_;
            split_pack(bp[0], bp[H_], h_, l_);
            sBh[n * RS + kp] = h_;
            sBl[n * RS + kp] = l_;
        }
        __syncthreads();

#pragma unroll
        for (int ks = 0; ks < 2; ks++) {
            int kp0 = ks * 8;
            unsigned bh[2][2], bl[2][2];
#pragma unroll
            for (int nf = 0; nf < 2; nf++) {
                int cb = (wn * 16 + nf * 8 + g) * RS + kp0 + tg;
                bh[nf][0] = sBh[cb]; bh[nf][1] = sBh[cb + 4];
                bl[nf][0] = sBl[cb]; bl[nf][1] = sBl[cb + 4];
            }
#pragma unroll
            for (int mf = 0; mf < 4; mf++) {
                int r0 = (wm * 64 + mf * 16 + g) * RS + kp0 + tg;
                int r1 = r0 + 8 * RS;
                unsigned ah[4] = {sAh[r0], sAh[r1], sAh[r0 + 4], sAh[r1 + 4]};
                unsigned al[4] = {sAl[r0], sAl[r1], sAl[r0 + 4], sAl[r1 + 4]};
#pragma unroll
                for (int nf = 0; nf < 2; nf++) {
                    MMA(cc[mf][nf], ah, bh[nf][0], bh[nf][1]);
                    MMA(cc[mf][nf], ah, bl[nf][0], bl[nf][1]);
                    MMA(cc[mf][nf], al, bh[nf][0], bh[nf][1]);
                }
            }
        }
        __syncthreads();
    }

#pragma unroll
    for (int mf = 0; mf < 4; mf++) {
        int rb = wm * 64 + mf * 16 + g;
#pragma unroll
        for (int half = 0; half < 2; half++) {
            int p = s_pair[rb + half * 8];
            if (p < 0) continue;
            int   t = p >> 1;
            float w = g_pair_w[p];
            float* dst = out + (size_t)t * H_ + n0glob + wn * 16 + 2 * tg;
#pragma unroll
            for (int nf = 0; nf < 2; nf++) {
                atomicAdd(&dst[nf * 8],     w * cc[mf][nf][half * 2 + 0]);
                atomicAdd(&dst[nf * 8 + 1], w * cc[mf][nf][half * 2 + 1]);
            }
        }
    }
}

// ---------------------------------------------------------------------------
extern "C" void kernel_launch(void* const* d_in, const int* in_sizes, int n_in,
                              void* d_out, int out_size) {
    const float* hid    = (const float*)d_in[0];   // [T, H]
    const float* logits = (const float*)d_in[1];   // [T, E]
    const float* W13    = (const float*)d_in[2];   // [E, H, 2I]
    const float* W2     = (const float*)d_in[3];   // [E, I, H]
    float* out = (float*)d_out;                    // [T, H]

    k_zero<<<(T_ * H_ / 4) / 256, 256>>>(out);
    k_route<<<1, 1024>>>(logits);

    dim3 g1(I_ / BN, E_ * MAXMT);
    k_gemm1<<<g1, 256>>>(hid, W13);
    dim3 g2(H_ / BN, E_ * MAXMT);
    k_gemm2<<<g2, 256>>>(W2, out);
}

// round 3
// speedup vs baseline: 1.9696x; 1.4624x over previous
#include <cuda_runtime.h>
#include <cuda_bf16.h>
#include <math.h>

#define T_ 1024
#define H_ 1024
#define I_ 1024
#define E_ 8
#define NP (T_*2)
#define HP (H_/2)      // 512 packed k-pairs
#define IP (I_/2)

#define BM 128
#define BN 64
#define BKP 16         // k-pairs per tile (BK = 32 floats)
#define RS 20          // A smem row stride (words) — conflict-free frags
#define BST 72         // B smem kp-row stride (words) — conflict-free frags
#define MAXMT 16

// ---- routing scratch ----
__device__ float g_pair_w[NP];
__device__ int   g_offsets[E_+1];
__device__ int   g_perm[NP];

// ---- packed bf16 hi/lo operands (uint32 = bf16x2 k-pair) ----
__device__ __align__(16) unsigned g_hidH[T_*HP],        g_hidL[T_*HP];        // [t][hp]
__device__ __align__(16) unsigned g_w13H[E_*HP*2*I_],   g_w13L[E_*HP*2*I_];   // [e][hp][2I]
__device__ __align__(16) unsigned g_w2H [E_*IP*H_],     g_w2L [E_*IP*H_];     // [e][ip][H]
__device__ __align__(16) unsigned g_actH[NP*IP],        g_actL[NP*IP];        // [p][ip]

// ---------------------------------------------------------------------------
__device__ __forceinline__ unsigned pack_rn(float x, float y) {
    __nv_bfloat162 v = __floats2bfloat162_rn(x, y);
    return *(unsigned*)&v;
}
__device__ __forceinline__ void split_pack(float x, float y, unsigned& hi, unsigned& lo) {
    hi = pack_rn(x, y);
    __nv_bfloat162 hv = *(__nv_bfloat162*)&hi;
    lo = pack_rn(x - __bfloat162float(hv.x), y - __bfloat162float(hv.y));
}

#define MMA(c, a, b0_, b1_)                                                   \
    asm volatile("mma.sync.aligned.m16n8k16.row.col.f32.bf16.bf16.f32 "       \
        "{%0,%1,%2,%3}, {%4,%5,%6,%7}, {%8,%9}, {%0,%1,%2,%3};"               \
        : "+f"((c)[0]), "+f"((c)[1]), "+f"((c)[2]), "+f"((c)[3])              \
        : "r"((a)[0]), "r"((a)[1]), "r"((a)[2]), "r"((a)[3]),                 \
          "r"(b0_), "r"(b1_))

// ---------------------------------------------------------------------------
__global__ void k_zero(float* __restrict__ out) {
    int i = blockIdx.x * blockDim.x + threadIdx.x;
    ((float4*)out)[i] = make_float4(0.f, 0.f, 0.f, 0.f);
}

// fused routing (one block of 1024 = T_)
__global__ void k_route(const float* __restrict__ logits) {
    __shared__ int cnt[E_], cur[E_], soff[E_ + 1];
    int t = threadIdx.x;
    if (t < E_) { cnt[t] = 0; cur[t] = 0; }
    __syncthreads();
    float l[E_];
#pragma unroll
    for (int e = 0; e < E_; e++) l[e] = logits[t * E_ + e];
    int i0 = 0;
#pragma unroll
    for (int e = 1; e < E_; e++) if (l[e] > l[i0]) i0 = e;
    int i1 = -1;
#pragma unroll
    for (int e = 0; e < E_; e++)
        if (e != i0 && (i1 < 0 || l[e] > l[i1])) i1 = e;
    float w0 = 1.f / (1.f + expf(l[i1] - l[i0]));
    float w1 = 1.f / (1.f + expf(l[i0] - l[i1]));
    g_pair_w[2 * t]     = w0;
    g_pair_w[2 * t + 1] = w1;
    atomicAdd(&cnt[i0], 1);
    atomicAdd(&cnt[i1], 1);
    __syncthreads();
    if (t == 0) {
        int o = 0;
        for (int e = 0; e < E_; e++) { soff[e] = o; o += cnt[e]; }
        soff[E_] = o;
    }
    __syncthreads();
    if (t <= E_) g_offsets[t] = soff[t];
    int p0 = atomicAdd(&cur[i0], 1);
    g_perm[soff[i0] + p0] = 2 * t;
    int p1 = atomicAdd(&cur[i1], 1);
    g_perm[soff[i1] + p1] = 2 * t + 1;
}

// ---------------------------------------------------------------------------
// pre-pass packing (all coalesced, x4 vectorized)
// ---------------------------------------------------------------------------
__global__ void k_pack_hid(const float* __restrict__ hid) {
    int i = blockIdx.x * 256 + threadIdx.x;           // T*HP/4 units
    const float4* s = (const float4*)hid + (size_t)i * 2;
    float4 a = s[0], b = s[1];
    uint4 Hh, Ll;
    split_pack(a.x, a.y, Hh.x, Ll.x);
    split_pack(a.z, a.w, Hh.y, Ll.y);
    split_pack(b.x, b.y, Hh.z, Ll.z);
    split_pack(b.z, b.w, Hh.w, Ll.w);
    ((uint4*)g_hidH)[i] = Hh;
    ((uint4*)g_hidL)[i] = Ll;
}

__global__ void k_pack_w13(const float* __restrict__ W) {
    size_t i = (size_t)blockIdx.x * 256 + threadIdx.x;  // 2M units (4 cols each)
    int f4 = (int)(i & 511);                            // 2I/4
    size_t r = i >> 9;
    int hp = (int)(r & (HP - 1));
    int e  = (int)(r >> 9);
    const float* base = W + ((size_t)e * H_ + 2 * hp) * (2 * I_) + f4 * 4;
    float4 a = *(const float4*)base;
    float4 b = *(const float4*)(base + 2 * I_);
    uint4 Hh, Ll;
    split_pack(a.x, b.x, Hh.x, Ll.x);
    split_pack(a.y, b.y, Hh.y, Ll.y);
    split_pack(a.z, b.z, Hh.z, Ll.z);
    split_pack(a.w, b.w, Hh.w, Ll.w);
    ((uint4*)g_w13H)[i] = Hh;
    ((uint4*)g_w13L)[i] = Ll;
}

__global__ void k_pack_w2(const float* __restrict__ W) {
    size_t i = (size_t)blockIdx.x * 256 + threadIdx.x;  // 1M units
    int f4 = (int)(i & 255);                            // H/4
    size_t r = i >> 8;
    int ip = (int)(r & (IP - 1));
    int e  = (int)(r >> 9);
    const float* base = W + ((size_t)e * I_ + 2 * ip) * H_ + f4 * 4;
    float4 a = *(const float4*)base;
    float4 b = *(const float4*)(base + H_);
    uint4 Hh, Ll;
    split_pack(a.x, b.x, Hh.x, Ll.x);
    split_pack(a.y, b.y, Hh.y, Ll.y);
    split_pack(a.z, b.z, Hh.z, Ll.z);
    split_pack(a.w, b.w, Hh.w, Ll.w);
    ((uint4*)g_w2H)[i] = Hh;
    ((uint4*)g_w2L)[i] = Ll;
}

// ---------------------------------------------------------------------------
// GEMM1: act = silu(X@Wg) * (X@Wu), register-pipelined HMMA, pure-copy staging
// ---------------------------------------------------------------------------
__global__ __launch_bounds__(256, 2) void k_gemm1() {
    __shared__ int s_pair[BM];
    __shared__ __align__(16) unsigned sAh[BM*RS], sAl[BM*RS];
    __shared__ __align__(16) unsigned sBgh[BKP*BST], sBgl[BKP*BST];
    __shared__ __align__(16) unsigned sBuh[BKP*BST], sBul[BKP*BST];

    int e  = blockIdx.y >> 4;
    int mt = blockIdx.y & 15;
    int off = g_offsets[e];
    int cnt = g_offsets[e + 1] - off;
    if (mt * BM >= cnt) return;

    int tid = threadIdx.x;
    if (tid < BM) {
        int r = mt * BM + tid;
        s_pair[tid] = (r < cnt) ? g_perm[off + r] : -1;
    }
    __syncthreads();

    int n0 = blockIdx.x * BN;
    const unsigned* WH = g_w13H + (size_t)e * HP * (2 * I_) + n0;
    const unsigned* WL = g_w13L + (size_t)e * HP * (2 * I_) + n0;

    int wid = tid >> 5, lane = tid & 31;
    int wm = wid >> 2, wn = wid & 3;          // 2 x 4 warps
    int g = lane >> 2, tg = lane & 3;
    int sm = tid >> 2, sj = (tid & 3) * 4;    // A staging: rows sm, sm+64
    int bn4 = (tid & 15) * 4, bkp = tid >> 4; // B staging

    float cg[4][2][4] = {}, cu[4][2][4] = {};
    uint4 rAh[2], rAl[2], rGh, rGl, rUh, rUl;

    auto LOAD = [&](int k0p) {
#pragma unroll
        for (int it = 0; it < 2; it++) {
            int p = s_pair[sm + it * 64];
            if (p >= 0) {
                size_t o = (size_t)(p >> 1) * HP + k0p + sj;
                rAh[it] = *(const uint4*)(g_hidH + o);
                rAl[it] = *(const uint4*)(g_hidL + o);
            } else {
                rAh[it] = make_uint4(0, 0, 0, 0);
                rAl[it] = make_uint4(0, 0, 0, 0);
            }
        }
        size_t bo = (size_t)(k0p + bkp) * (2 * I_) + bn4;
        rGh = *(const uint4*)(WH + bo);
        rGl = *(const uint4*)(WL + bo);
        rUh = *(const uint4*)(WH + bo + I_);
        rUl = *(const uint4*)(WL + bo + I_);
    };
    auto STORE = [&]() {
#pragma unroll
        for (int it = 0; it < 2; it++) {
            int m = sm + it * 64;
            *(uint4*)&sAh[m * RS + sj] = rAh[it];
            *(uint4*)&sAl[m * RS + sj] = rAl[it];
        }
        int b = bkp * BST + bn4;
        *(uint4*)&sBgh[b] = rGh;
        *(uint4*)&sBgl[b] = rGl;
        *(uint4*)&sBuh[b] = rUh;
        *(uint4*)&sBul[b] = rUl;
    };
    auto COMPUTE = [&]() {
#pragma unroll
        for (int ks = 0; ks < 2; ks++) {
            int kp0 = ks * 8;
            unsigned bgh[2][2], bgl[2][2], buh[2][2], bul[2][2];
#pragma unroll
            for (int nf = 0; nf < 2; nf++) {
                int c0 = (kp0 + tg) * BST + wn * 16 + nf * 8 + g;
                int c1 = c0 + 4 * BST;
                bgh[nf][0] = sBgh[c0]; bgh[nf][1] = sBgh[c1];
                bgl[nf][0] = sBgl[c0]; bgl[nf][1] = sBgl[c1];
                buh[nf][0] = sBuh[c0]; buh[nf][1] = sBuh[c1];
                bul[nf][0] = sBul[c0]; bul[nf][1] = sBul[c1];
            }
#pragma unroll
            for (int mf = 0; mf < 4; mf++) {
                int r0 = (wm * 64 + mf * 16 + g) * RS + kp0 + tg;
                int r1 = r0 + 8 * RS;
                unsigned ah[4] = {sAh[r0], sAh[r1], sAh[r0 + 4], sAh[r1 + 4]};
                unsigned al[4] = {sAl[r0], sAl[r1], sAl[r0 + 4], sAl[r1 + 4]};
#pragma unroll
                for (int nf = 0; nf < 2; nf++) {
                    MMA(cg[mf][nf], ah, bgh[nf][0], bgh[nf][1]);
                    MMA(cg[mf][nf], ah, bgl[nf][0], bgl[nf][1]);
                    MMA(cg[mf][nf], al, bgh[nf][0], bgh[nf][1]);
                    MMA(cu[mf][nf], ah, buh[nf][0], buh[nf][1]);
                    MMA(cu[mf][nf], ah, bul[nf][0], bul[nf][1]);
                    MMA(cu[mf][nf], al, buh[nf][0], buh[nf][1]);
                }
            }
        }
    };

    LOAD(0); STORE(); __syncthreads();
    for (int k0p = 0; k0p < HP; k0p += BKP) {
        int nxt = k0p + BKP;
        if (nxt < HP) LOAD(nxt);
        COMPUTE();
        if (nxt < HP) { __syncthreads(); STORE(); __syncthreads(); }
    }

    // epilogue: silu(gate)*up -> packed bf16 hi/lo act (k-pairs for gemm2)
    int pcb = (n0 >> 1) + wn * 8;
#pragma unroll
    for (int mf = 0; mf < 4; mf++) {
#pragma unroll
        for (int half = 0; half < 2; half++) {
            int p = s_pair[wm * 64 + mf * 16 + g + half * 8];
            if (p < 0) continue;
            size_t rowo = (size_t)p * IP;
#pragma unroll
            for (int nf = 0; nf < 2; nf++) {
                float g0 = cg[mf][nf][half * 2 + 0];
                float g1 = cg[mf][nf][half * 2 + 1];
                float u0 = cu[mf][nf][half * 2 + 0];
                float u1 = cu[mf][nf][half * 2 + 1];
                float a0 = u0 * g0 / (1.f + expf(-g0));
                float a1 = u1 * g1 / (1.f + expf(-g1));
                unsigned hh, ll;
                split_pack(a0, a1, hh, ll);
                int c = pcb + nf * 4 + tg;
                g_actH[rowo + c] = hh;
                g_actL[rowo + c] = ll;
            }
        }
    }
}

// ---------------------------------------------------------------------------
// GEMM2: out[t] += w_p * (act[p] @ W2[e]) — pure-copy staging, atomic scatter
// ---------------------------------------------------------------------------
__global__ __launch_bounds__(256, 2) void k_gemm2(float* __restrict__ out) {
    __shared__ int s_pair[BM];
    __shared__ __align__(16) unsigned sAh[BM*RS], sAl[BM*RS];
    __shared__ __align__(16) unsigned sBh[BKP*BST], sBl[BKP*BST];

    int e  = blockIdx.y >> 4;
    int mt = blockIdx.y & 15;
    int off = g_offsets[e];
    int cnt = g_offsets[e + 1] - off;
    if (mt * BM >= cnt) return;

    int tid = threadIdx.x;
    if (tid < BM) {
        int r = mt * BM + tid;
        s_pair[tid] = (r < cnt) ? g_perm[off + r] : -1;
    }
    __syncthreads();

    int n0 = blockIdx.x * BN;
    const unsigned* WH = g_w2H + (size_t)e * IP * H_ + n0;
    const unsigned* WL = g_w2L + (size_t)e * IP * H_ + n0;

    int wid = tid >> 5, lane = tid & 31;
    int wm = wid >> 2, wn = wid & 3;
    int g = lane >> 2, tg = lane & 3;
    int sm = tid >> 2, sj = (tid & 3) * 4;
    int bn4 = (tid & 15) * 4, bkp = tid >> 4;

    float cc[4][2][4] = {};
    uint4 rAh[2], rAl[2], rBh, rBl;

    auto LOAD = [&](int k0p) {
#pragma unroll
        for (int it = 0; it < 2; it++) {
            int p = s_pair[sm + it * 64];
            if (p >= 0) {
                size_t o = (size_t)p * IP + k0p + sj;
                rAh[it] = *(const uint4*)(g_actH + o);
                rAl[it] = *(const uint4*)(g_actL + o);
            } else {
                rAh[it] = make_uint4(0, 0, 0, 0);
                rAl[it] = make_uint4(0, 0, 0, 0);
            }
        }
        size_t bo = (size_t)(k0p + bkp) * H_ + bn4;
        rBh = *(const uint4*)(WH + bo);
        rBl = *(const uint4*)(WL + bo);
    };
    auto STORE = [&]() {
#pragma unroll
        for (int it = 0; it < 2; it++) {
            int m = sm + it * 64;
            *(uint4*)&sAh[m * RS + sj] = rAh[it];
            *(uint4*)&sAl[m * RS + sj] = rAl[it];
        }
        int b = bkp * BST + bn4;
        *(uint4*)&sBh[b] = rBh;
        *(uint4*)&sBl[b] = rBl;
    };
    auto COMPUTE = [&]() {
#pragma unroll
        for (int ks = 0; ks < 2; ks++) {
            int kp0 = ks * 8;
            unsigned bh[2][2], bl[2][2];
#pragma unroll
            for (int nf = 0; nf < 2; nf++) {
                int c0 = (kp0 + tg) * BST + wn * 16 + nf * 8 + g;
                int c1 = c0 + 4 * BST;
                bh[nf][0] = sBh[c0]; bh[nf][1] = sBh[c1];
                bl[nf][0] = sBl[c0]; bl[nf][1] = sBl[c1];
            }
#pragma unroll
            for (int mf = 0; mf < 4; mf++) {
                int r0 = (wm * 64 + mf * 16 + g) * RS + kp0 + tg;
                int r1 = r0 + 8 * RS;
                unsigned ah[4] = {sAh[r0], sAh[r1], sAh[r0 + 4], sAh[r1 + 4]};
                unsigned al[4] = {sAl[r0], sAl[r1], sAl[r0 + 4], sAl[r1 + 4]};
#pragma unroll
                for (int nf = 0; nf < 2; nf++) {
                    MMA(cc[mf][nf], ah, bh[nf][0], bh[nf][1]);
                    MMA(cc[mf][nf], ah, bl[nf][0], bl[nf][1]);
                    MMA(cc[mf][nf], al, bh[nf][0], bh[nf][1]);
                }
            }
        }
    };

    LOAD(0); STORE(); __syncthreads();
    for (int k0p = 0; k0p < IP; k0p += BKP) {
        int nxt = k0p + BKP;
        if (nxt < IP) LOAD(nxt);
        COMPUTE();
        if (nxt < IP) { __syncthreads(); STORE(); __syncthreads(); }
    }

#pragma unroll
    for (int mf = 0; mf < 4; mf++) {
#pragma unroll
        for (int half = 0; half < 2; half++) {
            int p = s_pair[wm * 64 + mf * 16 + g + half * 8];
            if (p < 0) continue;
            int   t = p >> 1;
            float w = g_pair_w[p];
            float* dst = out + (size_t)t * H_ + n0 + wn * 16 + 2 * tg;
#pragma unroll
            for (int nf = 0; nf < 2; nf++) {
                atomicAdd(&dst[nf * 8],     w * cc[mf][nf][half * 2 + 0]);
                atomicAdd(&dst[nf * 8 + 1], w * cc[mf][nf][half * 2 + 1]);
            }
        }
    }
}

// ---------------------------------------------------------------------------
extern "C" void kernel_launch(void* const* d_in, const int* in_sizes, int n_in,
                              void* d_out, int out_size) {
    const float* hid    = (const float*)d_in[0];   // [T, H]
    const float* logits = (const float*)d_in[1];   // [T, E]
    const float* W13    = (const float*)d_in[2];   // [E, H, 2I]
    const float* W2     = (const float*)d_in[3];   // [E, I, H]
    float* out = (float*)d_out;                    // [T, H]

    k_zero<<<(T_ * H_ / 4) / 256, 256>>>(out);
    k_route<<<1, 1024>>>(logits);
    k_pack_hid<<<(T_ * HP / 4) / 256, 256>>>(hid);
    k_pack_w13<<<(E_ * HP * 2 * I_ / 4) / 256, 256>>>(W13);
    k_pack_w2<<<(E_ * IP * H_ / 4) / 256, 256>>>(W2);

    dim3 g1(I_ / BN, E_ * MAXMT);
    k_gemm1<<<g1, 256>>>();
    dim3 g2(H_ / BN, E_ * MAXMT);
    k_gemm2<<<g2, 256>>>(out);
}

// round 5
// speedup vs baseline: 2.2583x; 1.1466x over previous
#include <cuda_runtime.h>
#include <cuda_bf16.h>
#include <math.h>
#include <stdint.h>

#define T_ 1024
#define H_ 1024
#define I_ 1024
#define E_ 8
#define NP (T_*2)
#define HP (H_/2)      // 512 packed k-pairs per row
#define IP (I_/2)

#define BM 128
#define BN 64
#define BKP 16         // k-pairs per chunk (32 floats)
#define RS 20          // A smem row stride (words) — conflict-free frags
#define BST 72         // B smem kp-row stride (words) — conflict-free frags
#define MAXMT 16
#define NCH1 (HP/BKP)  // 32 chunks
#define NCH2 (IP/BKP)

// stage word offsets (within one stage)
#define OFF_AH 0
#define OFF_AL 2560
#define OFF_B0 5120          // gemm1: Bgh ; gemm2: Bh
#define OFF_B1 6272          // gemm1: Bgl ; gemm2: Bl
#define OFF_B2 7424          // gemm1: Buh
#define OFF_B3 8576          // gemm1: Bul
#define STW1 9728            // stage words gemm1
#define STW2 7424            // stage words gemm2
#define SM1_BYTES ((128 + 2*STW1)*4)
#define SM2_BYTES ((128 + 2*STW2)*4)

// ---- routing scratch ----
__device__ float g_pair_w[NP];
__device__ int   g_offsets[E_+1];
__device__ int   g_perm[NP];

// ---- packed bf16 hi/lo operands (uint32 = bf16x2 k-pair) ----
__device__ __align__(16) unsigned g_hidH[T_*HP],        g_hidL[T_*HP];        // [t][hp]
__device__ __align__(16) unsigned g_w13H[E_*HP*2*I_],   g_w13L[E_*HP*2*I_];   // [e][hp][2I]
__device__ __align__(16) unsigned g_w2H [E_*IP*H_],     g_w2L [E_*IP*H_];     // [e][ip][H]
__device__ __align__(16) unsigned g_actH[NP*IP],        g_actL[NP*IP];        // [p][ip]

// ---------------------------------------------------------------------------
__device__ __forceinline__ unsigned pack_rn(float x, float y) {
    __nv_bfloat162 v = __floats2bfloat162_rn(x, y);
    return *(unsigned*)&v;
}
__device__ __forceinline__ void split_pack(float x, float y, unsigned& hi, unsigned& lo) {
    hi = pack_rn(x, y);
    __nv_bfloat162 hv = *(__nv_bfloat162*)&hi;
    lo = pack_rn(x - __bfloat162float(hv.x), y - __bfloat162float(hv.y));
}
__device__ __forceinline__ uint32_t smem_u32(const void* p) {
    uint32_t a;
    asm("{ .reg .u64 t; cvta.to.shared.u64 t, %1; cvt.u32.u64 %0, t; }" : "=r"(a) : "l"(p));
    return a;
}
#define CP16(dst, src, sz) \
    asm volatile("cp.async.cg.shared.global [%0], [%1], 16, %2;" :: "r"(dst), "l"(src), "r"(sz) : "memory")
#define CP_COMMIT() asm volatile("cp.async.commit_group;" ::: "memory")
#define CP_WAIT0()  asm volatile("cp.async.wait_group 0;" ::: "memory")

#define MMA(c, a, b0_, b1_)                                                   \
    asm volatile("mma.sync.aligned.m16n8k16.row.col.f32.bf16.bf16.f32 "       \
        "{%0,%1,%2,%3}, {%4,%5,%6,%7}, {%8,%9}, {%0,%1,%2,%3};"               \
        : "+f"((c)[0]), "+f"((c)[1]), "+f"((c)[2]), "+f"((c)[3])              \
        : "r"((a)[0]), "r"((a)[1]), "r"((a)[2]), "r"((a)[3]),                 \
          "r"(b0_), "r"(b1_))

// ---------------------------------------------------------------------------
// pack hidden (also zeroes out — same index space)
// ---------------------------------------------------------------------------
__global__ void k_pack_hid(const float* __restrict__ hid, float* __restrict__ out) {
    int i = blockIdx.x * 256 + threadIdx.x;           // T*HP/4 units
    const float4* s = (const float4*)hid + (size_t)i * 2;
    float4 a = s[0], b = s[1];
    uint4 Hh, Ll;
    split_pack(a.x, a.y, Hh.x, Ll.x);
    split_pack(a.z, a.w, Hh.y, Ll.y);
    split_pack(b.x, b.y, Hh.z, Ll.z);
    split_pack(b.z, b.w, Hh.w, Ll.w);
    ((uint4*)g_hidH)[i] = Hh;
    ((uint4*)g_hidL)[i] = Ll;
    float4 z = make_float4(0.f, 0.f, 0.f, 0.f);
    ((float4*)out)[2 * i]     = z;
    ((float4*)out)[2 * i + 1] = z;
}

__global__ void k_route(const float* __restrict__ logits) {
    __shared__ int cnt[E_], cur[E_], soff[E_ + 1];
    int t = threadIdx.x;
    if (t < E_) { cnt[t] = 0; cur[t] = 0; }
    __syncthreads();
    float l[E_];
#pragma unroll
    for (int e = 0; e < E_; e++) l[e] = logits[t * E_ + e];
    int i0 = 0;
#pragma unroll
    for (int e = 1; e < E_; e++) if (l[e] > l[i0]) i0 = e;
    int i1 = -1;
#pragma unroll
    for (int e = 0; e < E_; e++)
        if (e != i0 && (i1 < 0 || l[e] > l[i1])) i1 = e;
    g_pair_w[2 * t]     = 1.f / (1.f + expf(l[i1] - l[i0]));
    g_pair_w[2 * t + 1] = 1.f / (1.f + expf(l[i0] - l[i1]));
    atomicAdd(&cnt[i0], 1);
    atomicAdd(&cnt[i1], 1);
    __syncthreads();
    if (t == 0) {
        int o = 0;
        for (int e = 0; e < E_; e++) { soff[e] = o; o += cnt[e]; }
        soff[E_] = o;
    }
    __syncthreads();
    if (t <= E_) g_offsets[t] = soff[t];
    int p0 = atomicAdd(&cur[i0], 1);
    g_perm[soff[i0] + p0] = 2 * t;
    int p1 = atomicAdd(&cur[i1], 1);
    g_perm[soff[i1] + p1] = 2 * t + 1;
}

__global__ void k_pack_w13(const float* __restrict__ W) {
    size_t i = (size_t)blockIdx.x * 256 + threadIdx.x;  // E*HP*2I/4 units
    int f4 = (int)(i & 511);
    size_t r = i >> 9;
    int hp = (int)(r & (HP - 1));
    int e  = (int)(r >> 9);
    const float* base = W + ((size_t)e * H_ + 2 * hp) * (2 * I_) + f4 * 4;
    float4 a = *(const float4*)base;
    float4 b = *(const float4*)(base + 2 * I_);
    uint4 Hh, Ll;
    split_pack(a.x, b.x, Hh.x, Ll.x);
    split_pack(a.y, b.y, Hh.y, Ll.y);
    split_pack(a.z, b.z, Hh.z, Ll.z);
    split_pack(a.w, b.w, Hh.w, Ll.w);
    ((uint4*)g_w13H)[i] = Hh;
    ((uint4*)g_w13L)[i] = Ll;
}

__global__ void k_pack_w2(const float* __restrict__ W) {
    size_t i = (size_t)blockIdx.x * 256 + threadIdx.x;  // E*IP*H/4 units
    int f4 = (int)(i & 255);
    size_t r = i >> 8;
    int ip = (int)(r & (IP - 1));
    int e  = (int)(r >> 9);
    const float* base = W + ((size_t)e * I_ + 2 * ip) * H_ + f4 * 4;
    float4 a = *(const float4*)base;
    float4 b = *(const float4*)(base + H_);
    uint4 Hh, Ll;
    split_pack(a.x, b.x, Hh.x, Ll.x);
    split_pack(a.y, b.y, Hh.y, Ll.y);
    split_pack(a.z, b.z, Hh.z, Ll.z);
    split_pack(a.w, b.w, Hh.w, Ll.w);
    ((uint4*)g_w2H)[i] = Hh;
    ((uint4*)g_w2L)[i] = Ll;
}

// ---------------------------------------------------------------------------
// GEMM1: act = silu(X@Wg) * (X@Wu). cp.async 2-stage, ONE sync per chunk.
// ---------------------------------------------------------------------------
__global__ __launch_bounds__(256, 2) void k_gemm1() {
    extern __shared__ __align__(16) unsigned smem[];
    uint32_t sb = smem_u32(smem);
    int* s_pair = (int*)smem;                 // [128]

    int e  = blockIdx.y >> 4;
    int mt = blockIdx.y & 15;
    int off = g_offsets[e], cnt = g_offsets[e + 1] - off;
    if (mt * BM >= cnt) return;

    int tid = threadIdx.x;
    if (tid < BM) {
        int r = mt * BM + tid;
        s_pair[tid] = (r < cnt) ? g_perm[off + r] : -1;
    }
    __syncthreads();

    int n0 = blockIdx.x * BN;
    size_t we = (size_t)e * HP * (2 * I_);

    int wid = tid >> 5, lane = tid & 31;
    int wm = wid >> 2, wn = wid & 3;
    int g = lane >> 2, tg = lane & 3;
    int ar = tid >> 2, aseg = tid & 3;        // A staging
    int bkp = tid >> 4, bseg = tid & 15;      // B staging

    float cg[4][2][4] = {}, cu[4][2][4] = {};

    auto stage = [&](int c) {
        uint32_t s0 = sb + (128 + (c & 1) * STW1) * 4;
        int kof = c * BKP;
#pragma unroll
        for (int j = 0; j < 2; j++) {
            int m = ar + j * 64;
            int p = s_pair[m];
            uint32_t sz = (p >= 0) ? 16u : 0u;
            size_t so = (p >= 0) ? ((size_t)(p >> 1) * HP + kof + aseg * 4) : 0;
            CP16(s0 + (OFF_AH + m * RS + aseg * 4) * 4, g_hidH + so, sz);
            CP16(s0 + (OFF_AL + m * RS + aseg * 4) * 4, g_hidL + so, sz);
        }
        size_t bo = we + (size_t)(kof + bkp) * (2 * I_) + n0 + bseg * 4;
        uint32_t bd = s0 + (bkp * BST + bseg * 4) * 4;
        CP16(bd + OFF_B0 * 4, g_w13H + bo, 16);
        CP16(bd + OFF_B1 * 4, g_w13L + bo, 16);
        CP16(bd + OFF_B2 * 4, g_w13H + bo + I_, 16);
        CP16(bd + OFF_B3 * 4, g_w13L + bo + I_, 16);
        CP_COMMIT();
    };

    stage(0);
    for (int c = 0; c < NCH1; c++) {
        CP_WAIT0();
        __syncthreads();
        if (c + 1 < NCH1) { stage(c + 1); }
        unsigned* st = smem + 128 + (c & 1) * STW1;
#pragma unroll
        for (int ks = 0; ks < 2; ks++) {
            int kp0 = ks * 8;
            unsigned bgh[2][2], bgl[2][2], buh[2][2], bul[2][2];
#pragma unroll
            for (int nf = 0; nf < 2; nf++) {
                int c0 = (kp0 + tg) * BST + wn * 16 + nf * 8 + g;
                int c1 = c0 + 4 * BST;
                bgh[nf][0] = st[OFF_B0 + c0]; bgh[nf][1] = st[OFF_B0 + c1];
                bgl[nf][0] = st[OFF_B1 + c0]; bgl[nf][1] = st[OFF_B1 + c1];
                buh[nf][0] = st[OFF_B2 + c0]; buh[nf][1] = st[OFF_B2 + c1];
                bul[nf][0] = st[OFF_B3 + c0]; bul[nf][1] = st[OFF_B3 + c1];
            }
#pragma unroll
            for (int mf = 0; mf < 4; mf++) {
                int r0 = (wm * 64 + mf * 16 + g) * RS + kp0 + tg;
                int r1 = r0 + 8 * RS;
                unsigned ah[4] = {st[OFF_AH+r0], st[OFF_AH+r1], st[OFF_AH+r0+4], st[OFF_AH+r1+4]};
                unsigned al[4] = {st[OFF_AL+r0], st[OFF_AL+r1], st[OFF_AL+r0+4], st[OFF_AL+r1+4]};
#pragma unroll
                for (int nf = 0; nf < 2; nf++) {
                    MMA(cg[mf][nf], ah, bgh[nf][0], bgh[nf][1]);
                    MMA(cg[mf][nf], ah, bgl[nf][0], bgl[nf][1]);
                    MMA(cg[mf][nf], al, bgh[nf][0], bgh[nf][1]);
                    MMA(cu[mf][nf], ah, buh[nf][0], buh[nf][1]);
                    MMA(cu[mf][nf], ah, bul[nf][0], bul[nf][1]);
                    MMA(cu[mf][nf], al, buh[nf][0], buh[nf][1]);
                }
            }
        }
    }

    // epilogue: silu(gate)*up -> packed bf16 hi/lo act (k-pairs for gemm2)
    int pcb = (n0 >> 1) + wn * 8;
#pragma unroll
    for (int mf = 0; mf < 4; mf++) {
#pragma unroll
        for (int half = 0; half < 2; half++) {
            int p = s_pair[wm * 64 + mf * 16 + g + half * 8];
            if (p < 0) continue;
            size_t rowo = (size_t)p * IP;
#pragma unroll
            for (int nf = 0; nf < 2; nf++) {
                float g0 = cg[mf][nf][half * 2 + 0];
                float g1 = cg[mf][nf][half * 2 + 1];
                float u0 = cu[mf][nf][half * 2 + 0];
                float u1 = cu[mf][nf][half * 2 + 1];
                float a0 = u0 * g0 / (1.f + expf(-g0));
                float a1 = u1 * g1 / (1.f + expf(-g1));
                unsigned hh, ll;
                split_pack(a0, a1, hh, ll);
                int c = pcb + nf * 4 + tg;
                g_actH[rowo + c] = hh;
                g_actL[rowo + c] = ll;
            }
        }
    }
}

// ---------------------------------------------------------------------------
// GEMM2: out[t] += w_p * (act[p] @ W2[e]); cp.async 2-stage, one sync/chunk
// ---------------------------------------------------------------------------
__global__ __launch_bounds__(256, 2) void k_gemm2(float* __restrict__ out) {
    extern __shared__ __align__(16) unsigned smem[];
    uint32_t sb = smem_u32(smem);
    int* s_pair = (int*)smem;

    int e  = blockIdx.y >> 4;
    int mt = blockIdx.y & 15;
    int off = g_offsets[e], cnt = g_offsets[e + 1] - off;
    if (mt * BM >= cnt) return;

    int tid = threadIdx.x;
    if (tid < BM) {
        int r = mt * BM + tid;
        s_pair[tid] = (r < cnt) ? g_perm[off + r] : -1;
    }
    __syncthreads();

    int n0 = blockIdx.x * BN;
    size_t we = (size_t)e * IP * H_;

    int wid = tid >> 5, lane = tid & 31;
    int wm = wid >> 2, wn = wid & 3;
    int g = lane >> 2, tg = lane & 3;
    int ar = tid >> 2, aseg = tid & 3;
    int bkp = tid >> 4, bseg = tid & 15;

    float cc[4][2][4] = {};

    auto stage = [&](int c) {
        uint32_t s0 = sb + (128 + (c & 1) * STW2) * 4;
        int kof = c * BKP;
#pragma unroll
        for (int j = 0; j < 2; j++) {
            int m = ar + j * 64;
            int p = s_pair[m];
            uint32_t sz = (p >= 0) ? 16u : 0u;
            size_t so = (p >= 0) ? ((size_t)p * IP + kof + aseg * 4) : 0;
            CP16(s0 + (OFF_AH + m * RS + aseg * 4) * 4, g_actH + so, sz);
            CP16(s0 + (OFF_AL + m * RS + aseg * 4) * 4, g_actL + so, sz);
        }
        size_t bo = we + (size_t)(kof + bkp) * H_ + n0 + bseg * 4;
        uint32_t bd = s0 + (bkp * BST + bseg * 4) * 4;
        CP16(bd + OFF_B0 * 4, g_w2H + bo, 16);
        CP16(bd + OFF_B1 * 4, g_w2L + bo, 16);
        CP_COMMIT();
    };

    stage(0);
    for (int c = 0; c < NCH2; c++) {
        CP_WAIT0();
        __syncthreads();
        if (c + 1 < NCH2) { stage(c + 1); }
        unsigned* st = smem + 128 + (c & 1) * STW2;
#pragma unroll
        for (int ks = 0; ks < 2; ks++) {
            int kp0 = ks * 8;
            unsigned bh[2][2], bl[2][2];
#pragma unroll
            for (int nf = 0; nf < 2; nf++) {
                int c0 = (kp0 + tg) * BST + wn * 16 + nf * 8 + g;
                int c1 = c0 + 4 * BST;
                bh[nf][0] = st[OFF_B0 + c0]; bh[nf][1] = st[OFF_B0 + c1];
                bl[nf][0] = st[OFF_B1 + c0]; bl[nf][1] = st[OFF_B1 + c1];
            }
#pragma unroll
            for (int mf = 0; mf < 4; mf++) {
                int r0 = (wm * 64 + mf * 16 + g) * RS + kp0 + tg;
                int r1 = r0 + 8 * RS;
                unsigned ah[4] = {st[OFF_AH+r0], st[OFF_AH+r1], st[OFF_AH+r0+4], st[OFF_AH+r1+4]};
                unsigned al[4] = {st[OFF_AL+r0], st[OFF_AL+r1], st[OFF_AL+r0+4], st[OFF_AL+r1+4]};
#pragma unroll
                for (int nf = 0; nf < 2; nf++) {
                    MMA(cc[mf][nf], ah, bh[nf][0], bh[nf][1]);
                    MMA(cc[mf][nf], ah, bl[nf][0], bl[nf][1]);
                    MMA(cc[mf][nf], al, bh[nf][0], bh[nf][1]);
                }
            }
        }
    }

#pragma unroll
    for (int mf = 0; mf < 4; mf++) {
#pragma unroll
        for (int half = 0; half < 2; half++) {
            int p = s_pair[wm * 64 + mf * 16 + g + half * 8];
            if (p < 0) continue;
            int   t = p >> 1;
            float w = g_pair_w[p];
            float* dst = out + (size_t)t * H_ + n0 + wn * 16 + 2 * tg;
#pragma unroll
            for (int nf = 0; nf < 2; nf++) {
                atomicAdd(&dst[nf * 8],     w * cc[mf][nf][half * 2 + 0]);
                atomicAdd(&dst[nf * 8 + 1], w * cc[mf][nf][half * 2 + 1]);
            }
        }
    }
}

// ---------------------------------------------------------------------------
extern "C" void kernel_launch(void* const* d_in, const int* in_sizes, int n_in,
                              void* d_out, int out_size) {
    const float* hid    = (const float*)d_in[0];   // [T, H]
    const float* logits = (const float*)d_in[1];   // [T, E]
    const float* W13    = (const float*)d_in[2];   // [E, H, 2I]
    const float* W2     = (const float*)d_in[3];   // [E, I, H]
    float* out = (float*)d_out;                    // [T, H]

    cudaFuncSetAttribute(k_gemm1, cudaFuncAttributeMaxDynamicSharedMemorySize, SM1_BYTES);
    cudaFuncSetAttribute(k_gemm2, cudaFuncAttributeMaxDynamicSharedMemorySize, SM2_BYTES);

    k_pack_hid<<<(T_ * HP / 4) / 256, 256>>>(hid, out);
    k_route<<<1, 1024>>>(logits);
    k_pack_w13<<<(E_ * HP * 2 * I_ / 4) / 256, 256>>>(W13);
    k_pack_w2<<<(E_ * IP * H_ / 4) / 256, 256>>>(W2);

    dim3 g1(I_ / BN, E_ * MAXMT);
    k_gemm1<<<g1, 256, SM1_BYTES>>>();
    dim3 g2(H_ / BN, E_ * MAXMT);
    k_gemm2<<<g2, 256, SM2_BYTES>>>(out);
}

// round 6
// speedup vs baseline: 2.3404x; 1.0364x over previous
#include <cuda_runtime.h>
#include <cuda_fp16.h>
#include <math.h>
#include <stdint.h>

#define T_ 1024
#define H_ 1024
#define I_ 1024
#define E_ 8
#define NP (T_*2)
#define HP (H_/2)      // 512 packed k-pairs per row
#define IP (I_/2)

#define BM 128
#define BN 64
#define BKP 16         // k-pairs per chunk (32 floats)
#define RS 20          // A smem row stride (words) — conflict-free frags
#define BST 72         // B smem kp-row stride (words) — conflict-free frags
#define MAXMT 16
#define NCH1 (HP/BKP)  // 32 chunks
#define NCH2 (IP/BKP)

// combine constants: D = (1 - 1/s)*C_HH + s*C_MM, s = 32
#define SC_C 0.96875f
#define SC_S 32.0f
#define SC_INV 0.03125f

// stage word offsets (within one stage)
#define OFF_AH 0
#define OFF_AM 2560
#define OFF_B0 5120          // gemm1: gate-H ; gemm2: w2-H
#define OFF_B1 6272          // gemm1: gate-M ; gemm2: w2-M
#define OFF_B2 7424          // gemm1: up-H
#define OFF_B3 8576          // gemm1: up-M
#define STW1 9728            // stage words gemm1
#define STW2 7424            // stage words gemm2
#define SM1_BYTES ((128 + 2*STW1)*4)
#define SM2_BYTES ((128 + 2*STW2)*4)

// ---- routing scratch ----
__device__ float g_pair_w[NP];
__device__ int   g_offsets[E_+1];
__device__ int   g_perm[NP];

// ---- packed fp16 hi / scaled-residual operands (uint32 = half2 k-pair) ----
__device__ __align__(16) unsigned g_hidH[T_*HP],        g_hidM[T_*HP];        // [t][hp]
__device__ __align__(16) unsigned g_w13H[E_*HP*2*I_],   g_w13M[E_*HP*2*I_];   // [e][hp][2I]
__device__ __align__(16) unsigned g_w2H [E_*IP*H_],     g_w2M [E_*IP*H_];     // [e][ip][H]
__device__ __align__(16) unsigned g_actH[NP*IP],        g_actM[NP*IP];        // [p][ip]

// ---------------------------------------------------------------------------
__device__ __forceinline__ void split_pack16(float x, float y, unsigned& h, unsigned& m) {
    __half2 hv = __floats2half2_rn(x, y);
    h = *(unsigned*)&hv;
    float hx = __low2float(hv), hy = __high2float(hv);
    float mx = hx * SC_INV + (x - hx);
    float my = hy * SC_INV + (y - hy);
    __half2 mv = __floats2half2_rn(mx, my);
    m = *(unsigned*)&mv;
}
__device__ __forceinline__ uint32_t smem_u32(const void* p) {
    uint32_t a;
    asm("{ .reg .u64 t; cvta.to.shared.u64 t, %1; cvt.u32.u64 %0, t; }" : "=r"(a) : "l"(p));
    return a;
}
#define CP16(dst, src, sz) \
    asm volatile("cp.async.cg.shared.global [%0], [%1], 16, %2;" :: "r"(dst), "l"(src), "r"(sz) : "memory")
#define CP_COMMIT() asm volatile("cp.async.commit_group;" ::: "memory")
#define CP_WAIT0()  asm volatile("cp.async.wait_group 0;" ::: "memory")

#define MMA(c, a, b0_, b1_)                                                   \
    asm volatile("mma.sync.aligned.m16n8k16.row.col.f32.f16.f16.f32 "         \
        "{%0,%1,%2,%3}, {%4,%5,%6,%7}, {%8,%9}, {%0,%1,%2,%3};"               \
        : "+f"((c)[0]), "+f"((c)[1]), "+f"((c)[2]), "+f"((c)[3])              \
        : "r"((a)[0]), "r"((a)[1]), "r"((a)[2]), "r"((a)[3]),                 \
          "r"(b0_), "r"(b1_))

// ---------------------------------------------------------------------------
// pack hidden (also zeroes out — same index space)
// ---------------------------------------------------------------------------
__global__ void k_pack_hid(const float* __restrict__ hid, float* __restrict__ out) {
    int i = blockIdx.x * 256 + threadIdx.x;           // T*HP/4 units
    const float4* s = (const float4*)hid + (size_t)i * 2;
    float4 a = s[0], b = s[1];
    uint4 Hh, Mm;
    split_pack16(a.x, a.y, Hh.x, Mm.x);
    split_pack16(a.z, a.w, Hh.y, Mm.y);
    split_pack16(b.x, b.y, Hh.z, Mm.z);
    split_pack16(b.z, b.w, Hh.w, Mm.w);
    ((uint4*)g_hidH)[i] = Hh;
    ((uint4*)g_hidM)[i] = Mm;
    float4 z = make_float4(0.f, 0.f, 0.f, 0.f);
    ((float4*)out)[2 * i]     = z;
    ((float4*)out)[2 * i + 1] = z;
}

__global__ void k_route(const float* __restrict__ logits) {
    __shared__ int cnt[E_], cur[E_], soff[E_ + 1];
    int t = threadIdx.x;
    if (t < E_) { cnt[t] = 0; cur[t] = 0; }
    __syncthreads();
    float l[E_];
#pragma unroll
    for (int e = 0; e < E_; e++) l[e] = logits[t * E_ + e];
    int i0 = 0;
#pragma unroll
    for (int e = 1; e < E_; e++) if (l[e] > l[i0]) i0 = e;
    int i1 = -1;
#pragma unroll
    for (int e = 0; e < E_; e++)
        if (e != i0 && (i1 < 0 || l[e] > l[i1])) i1 = e;
    g_pair_w[2 * t]     = 1.f / (1.f + expf(l[i1] - l[i0]));
    g_pair_w[2 * t + 1] = 1.f / (1.f + expf(l[i0] - l[i1]));
    atomicAdd(&cnt[i0], 1);
    atomicAdd(&cnt[i1], 1);
    __syncthreads();
    if (t == 0) {
        int o = 0;
        for (int e = 0; e < E_; e++) { soff[e] = o; o += cnt[e]; }
        soff[E_] = o;
    }
    __syncthreads();
    if (t <= E_) g_offsets[t] = soff[t];
    int p0 = atomicAdd(&cur[i0], 1);
    g_perm[soff[i0] + p0] = 2 * t;
    int p1 = atomicAdd(&cur[i1], 1);
    g_perm[soff[i1] + p1] = 2 * t + 1;
}

// merged weight packing: blocks [0, NB13) -> W13, [NB13, NB13+NB2) -> W2
#define NB13 (E_ * HP * 2 * I_ / 4 / 256)
#define NB2  (E_ * IP * H_ / 4 / 256)
__global__ void k_pack_w(const float* __restrict__ W13, const float* __restrict__ W2) {
    if (blockIdx.x < NB13) {
        size_t i = (size_t)blockIdx.x * 256 + threadIdx.x;
        int f4 = (int)(i & 511);
        size_t r = i >> 9;
        int hp = (int)(r & (HP - 1));
        int e  = (int)(r >> 9);
        const float* base = W13 + ((size_t)e * H_ + 2 * hp) * (2 * I_) + f4 * 4;
        float4 a = *(const float4*)base;
        float4 b = *(const float4*)(base + 2 * I_);
        uint4 Hh, Mm;
        split_pack16(a.x, b.x, Hh.x, Mm.x);
        split_pack16(a.y, b.y, Hh.y, Mm.y);
        split_pack16(a.z, b.z, Hh.z, Mm.z);
        split_pack16(a.w, b.w, Hh.w, Mm.w);
        ((uint4*)g_w13H)[i] = Hh;
        ((uint4*)g_w13M)[i] = Mm;
    } else {
        size_t i = (size_t)(blockIdx.x - NB13) * 256 + threadIdx.x;
        int f4 = (int)(i & 255);
        size_t r = i >> 8;
        int ip = (int)(r & (IP - 1));
        int e  = (int)(r >> 9);
        const float* base = W2 + ((size_t)e * I_ + 2 * ip) * H_ + f4 * 4;
        float4 a = *(const float4*)base;
        float4 b = *(const float4*)(base + H_);
        uint4 Hh, Mm;
        split_pack16(a.x, b.x, Hh.x, Mm.x);
        split_pack16(a.y, b.y, Hh.y, Mm.y);
        split_pack16(a.z, b.z, Hh.z, Mm.z);
        split_pack16(a.w, b.w, Hh.w, Mm.w);
        ((uint4*)g_w2H)[i] = Hh;
        ((uint4*)g_w2M)[i] = Mm;
    }
}

// ---------------------------------------------------------------------------
// GEMM1: act = silu(X@Wg) * (X@Wu). 2-MMA fp16 split, cp.async 2-stage.
// ---------------------------------------------------------------------------
__global__ __launch_bounds__(256, 1) void k_gemm1() {
    extern __shared__ __align__(16) unsigned smem[];
    uint32_t sb = smem_u32(smem);
    int* s_pair = (int*)smem;                 // [128]

    int e  = blockIdx.y >> 4;
    int mt = blockIdx.y & 15;
    int off = g_offsets[e], cnt = g_offsets[e + 1] - off;
    if (mt * BM >= cnt) return;

    int tid = threadIdx.x;
    if (tid < BM) {
        int r = mt * BM + tid;
        s_pair[tid] = (r < cnt) ? g_perm[off + r] : -1;
    }
    __syncthreads();

    int n0 = blockIdx.x * BN;
    size_t we = (size_t)e * HP * (2 * I_);

    int wid = tid >> 5, lane = tid & 31;
    int wm = wid >> 2, wn = wid & 3;
    int g = lane >> 2, tg = lane & 3;
    int ar = tid >> 2, aseg = tid & 3;        // A staging
    int bkp = tid >> 4, bseg = tid & 15;      // B staging

    float cgH[4][2][4] = {}, cgM[4][2][4] = {};
    float cuH[4][2][4] = {}, cuM[4][2][4] = {};

    auto stage = [&](int c) {
        uint32_t s0 = sb + (128 + (c & 1) * STW1) * 4;
        int kof = c * BKP;
#pragma unroll
        for (int j = 0; j < 2; j++) {
            int m = ar + j * 64;
            int p = s_pair[m];
            uint32_t sz = (p >= 0) ? 16u : 0u;
            size_t so = (p >= 0) ? ((size_t)(p >> 1) * HP + kof + aseg * 4) : 0;
            CP16(s0 + (OFF_AH + m * RS + aseg * 4) * 4, g_hidH + so, sz);
            CP16(s0 + (OFF_AM + m * RS + aseg * 4) * 4, g_hidM + so, sz);
        }
        size_t bo = we + (size_t)(kof + bkp) * (2 * I_) + n0 + bseg * 4;
        uint32_t bd = s0 + (bkp * BST + bseg * 4) * 4;
        CP16(bd + OFF_B0 * 4, g_w13H + bo, 16);
        CP16(bd + OFF_B1 * 4, g_w13M + bo, 16);
        CP16(bd + OFF_B2 * 4, g_w13H + bo + I_, 16);
        CP16(bd + OFF_B3 * 4, g_w13M + bo + I_, 16);
        CP_COMMIT();
    };

    stage(0);
    for (int c = 0; c < NCH1; c++) {
        CP_WAIT0();
        __syncthreads();
        if (c + 1 < NCH1) { stage(c + 1); }
        unsigned* st = smem + 128 + (c & 1) * STW1;
#pragma unroll
        for (int ks = 0; ks < 2; ks++) {
            int kp0 = ks * 8;
            unsigned bgh[2][2], bgm[2][2], buh[2][2], bum[2][2];
#pragma unroll
            for (int nf = 0; nf < 2; nf++) {
                int c0 = (kp0 + tg) * BST + wn * 16 + nf * 8 + g;
                int c1 = c0 + 4 * BST;
                bgh[nf][0] = st[OFF_B0 + c0]; bgh[nf][1] = st[OFF_B0 + c1];
                bgm[nf][0] = st[OFF_B1 + c0]; bgm[nf][1] = st[OFF_B1 + c1];
                buh[nf][0] = st[OFF_B2 + c0]; buh[nf][1] = st[OFF_B2 + c1];
                bum[nf][0] = st[OFF_B3 + c0]; bum[nf][1] = st[OFF_B3 + c1];
            }
#pragma unroll
            for (int mf = 0; mf < 4; mf++) {
                int r0 = (wm * 64 + mf * 16 + g) * RS + kp0 + tg;
                int r1 = r0 + 8 * RS;
                unsigned ah[4] = {st[OFF_AH+r0], st[OFF_AH+r1], st[OFF_AH+r0+4], st[OFF_AH+r1+4]};
                unsigned am[4] = {st[OFF_AM+r0], st[OFF_AM+r1], st[OFF_AM+r0+4], st[OFF_AM+r1+4]};
#pragma unroll
                for (int nf = 0; nf < 2; nf++) {
                    MMA(cgH[mf][nf], ah, bgh[nf][0], bgh[nf][1]);
                    MMA(cgM[mf][nf], am, bgm[nf][0], bgm[nf][1]);
                    MMA(cuH[mf][nf], ah, buh[nf][0], buh[nf][1]);
                    MMA(cuM[mf][nf], am, bum[nf][0], bum[nf][1]);
                }
            }
        }
    }

    // epilogue: combine, silu(gate)*up -> packed fp16 H/M act
    int pcb = (n0 >> 1) + wn * 8;
#pragma unroll
    for (int mf = 0; mf < 4; mf++) {
#pragma unroll
        for (int half = 0; half < 2; half++) {
            int p = s_pair[wm * 64 + mf * 16 + g + half * 8];
            if (p < 0) continue;
            size_t rowo = (size_t)p * IP;
#pragma unroll
            for (int nf = 0; nf < 2; nf++) {
                float g0 = SC_C * cgH[mf][nf][half*2+0] + SC_S * cgM[mf][nf][half*2+0];
                float g1 = SC_C * cgH[mf][nf][half*2+1] + SC_S * cgM[mf][nf][half*2+1];
                float u0 = SC_C * cuH[mf][nf][half*2+0] + SC_S * cuM[mf][nf][half*2+0];
                float u1 = SC_C * cuH[mf][nf][half*2+1] + SC_S * cuM[mf][nf][half*2+1];
                float a0 = u0 * g0 / (1.f + expf(-g0));
                float a1 = u1 * g1 / (1.f + expf(-g1));
                unsigned hh, mm;
                split_pack16(a0, a1, hh, mm);
                int c = pcb + nf * 4 + tg;
                g_actH[rowo + c] = hh;
                g_actM[rowo + c] = mm;
            }
        }
    }
}

// ---------------------------------------------------------------------------
// GEMM2: out[t] += w_p * (act[p] @ W2[e]); 2-MMA fp16 split
// ---------------------------------------------------------------------------
__global__ __launch_bounds__(256, 2) void k_gemm2(float* __restrict__ out) {
    extern __shared__ __align__(16) unsigned smem[];
    uint32_t sb = smem_u32(smem);
    int* s_pair = (int*)smem;

    int e  = blockIdx.y >> 4;
    int mt = blockIdx.y & 15;
    int off = g_offsets[e], cnt = g_offsets[e + 1] - off;
    if (mt * BM >= cnt) return;

    int tid = threadIdx.x;
    if (tid < BM) {
        int r = mt * BM + tid;
        s_pair[tid] = (r < cnt) ? g_perm[off + r] : -1;
    }
    __syncthreads();

    int n0 = blockIdx.x * BN;
    size_t we = (size_t)e * IP * H_;

    int wid = tid >> 5, lane = tid & 31;
    int wm = wid >> 2, wn = wid & 3;
    int g = lane >> 2, tg = lane & 3;
    int ar = tid >> 2, aseg = tid & 3;
    int bkp = tid >> 4, bseg = tid & 15;

    float ccH[4][2][4] = {}, ccM[4][2][4] = {};

    auto stage = [&](int c) {
        uint32_t s0 = sb + (128 + (c & 1) * STW2) * 4;
        int kof = c * BKP;
#pragma unroll
        for (int j = 0; j < 2; j++) {
            int m = ar + j * 64;
            int p = s_pair[m];
            uint32_t sz = (p >= 0) ? 16u : 0u;
            size_t so = (p >= 0) ? ((size_t)p * IP + kof + aseg * 4) : 0;
            CP16(s0 + (OFF_AH + m * RS + aseg * 4) * 4, g_actH + so, sz);
            CP16(s0 + (OFF_AM + m * RS + aseg * 4) * 4, g_actM + so, sz);
        }
        size_t bo = we + (size_t)(kof + bkp) * H_ + n0 + bseg * 4;
        uint32_t bd = s0 + (bkp * BST + bseg * 4) * 4;
        CP16(bd + OFF_B0 * 4, g_w2H + bo, 16);
        CP16(bd + OFF_B1 * 4, g_w2M + bo, 16);
        CP_COMMIT();
    };

    stage(0);
    for (int c = 0; c < NCH2; c++) {
        CP_WAIT0();
        __syncthreads();
        if (c + 1 < NCH2) { stage(c + 1); }
        unsigned* st = smem + 128 + (c & 1) * STW2;
#pragma unroll
        for (int ks = 0; ks < 2; ks++) {
            int kp0 = ks * 8;
            unsigned bh[2][2], bm[2][2];
#pragma unroll
            for (int nf = 0; nf < 2; nf++) {
                int c0 = (kp0 + tg) * BST + wn * 16 + nf * 8 + g;
                int c1 = c0 + 4 * BST;
                bh[nf][0] = st[OFF_B0 + c0]; bh[nf][1] = st[OFF_B0 + c1];
                bm[nf][0] = st[OFF_B1 + c0]; bm[nf][1] = st[OFF_B1 + c1];
            }
#pragma unroll
            for (int mf = 0; mf < 4; mf++) {
                int r0 = (wm * 64 + mf * 16 + g) * RS + kp0 + tg;
                int r1 = r0 + 8 * RS;
                unsigned ah[4] = {st[OFF_AH+r0], st[OFF_AH+r1], st[OFF_AH+r0+4], st[OFF_AH+r1+4]};
                unsigned am[4] = {st[OFF_AM+r0], st[OFF_AM+r1], st[OFF_AM+r0+4], st[OFF_AM+r1+4]};
#pragma unroll
                for (int nf = 0; nf < 2; nf++) {
                    MMA(ccH[mf][nf], ah, bh[nf][0], bh[nf][1]);
                    MMA(ccM[mf][nf], am, bm[nf][0], bm[nf][1]);
                }
            }
        }
    }

#pragma unroll
    for (int mf = 0; mf < 4; mf++) {
#pragma unroll
        for (int half = 0; half < 2; half++) {
            int p = s_pair[wm * 64 + mf * 16 + g + half * 8];
            if (p < 0) continue;
            int   t = p >> 1;
            float w = g_pair_w[p];
            float* dst = out + (size_t)t * H_ + n0 + wn * 16 + 2 * tg;
#pragma unroll
            for (int nf = 0; nf < 2; nf++) {
                float r0 = SC_C * ccH[mf][nf][half*2+0] + SC_S * ccM[mf][nf][half*2+0];
                float r1 = SC_C * ccH[mf][nf][half*2+1] + SC_S * ccM[mf][nf][half*2+1];
                atomicAdd(&dst[nf * 8],     w * r0);
                atomicAdd(&dst[nf * 8 + 1], w * r1);
            }
        }
    }
}

// ---------------------------------------------------------------------------
extern "C" void kernel_launch(void* const* d_in, const int* in_sizes, int n_in,
                              void* d_out, int out_size) {
    const float* hid    = (const float*)d_in[0];   // [T, H]
    const float* logits = (const float*)d_in[1];   // [T, E]
    const float* W13    = (const float*)d_in[2];   // [E, H, 2I]
    const float* W2     = (const float*)d_in[3];   // [E, I, H]
    float* out = (float*)d_out;                    // [T, H]

    cudaFuncSetAttribute(k_gemm1, cudaFuncAttributeMaxDynamicSharedMemorySize, SM1_BYTES);
    cudaFuncSetAttribute(k_gemm2, cudaFuncAttributeMaxDynamicSharedMemorySize, SM2_BYTES);

    k_pack_hid<<<(T_ * HP / 4) / 256, 256>>>(hid, out);
    k_route<<<1, 1024>>>(logits);
    k_pack_w<<<NB13 + NB2, 256>>>(W13, W2);

    dim3 g1(I_ / BN, E_ * MAXMT);
    k_gemm1<<<g1, 256, SM1_BYTES>>>();
    dim3 g2(H_ / BN, E_ * MAXMT);
    k_gemm2<<<g2, 256, SM2_BYTES>>>(out);
}